// round 12
// baseline (speedup 1.0000x reference)
#include <cuda_runtime.h>
#include <cuda_fp16.h>
#include <math.h>
#include <stdint.h>

// ---------------- problem constants ----------------
constexpr int CB  = 4;
constexpr int CT  = 2048;
constexpr int CDM = 768;
constexpr int CDI = 1536;
constexpr int CN  = 64;
constexpr int CR  = 48;
constexpr int CPW = CR + 2*CN;      // 176
constexpr int CBT   = CB*CT;        // 8192
constexpr int CBTDM = CBT*CDM;
constexpr int CBTDI = CBT*CDI;

constexpr int NIW = 2*2*CDI*CDM;
constexpr int NXW = 2*CPW*CDI;
constexpr int NDW = 2*CDI*CR;
constexpr int NOW = 2*CDM*CDI;

#define LOG2E_F 1.4426950408889634f

// ---------------- fp32 scratch ----------------
__device__ float g_x   [CBTDM];
__device__ float g_uc  [CBTDI];
__device__ float g_proj[CBT*CPW];
__device__ float g_del [CBTDI];
__device__ float g_ho  [CBTDM];

// ---------------- fp16 planes ----------------
__device__ __half g_xza[CBT*2*CDI];   // in_proj output (u|z) fp16
__device__ __half g_xa [CBTDM];
__device__ __half g_uca[CBTDI];
__device__ __half g_dta[CBT*CR];
__device__ __half g_ya [CBTDI];
// fp16 weights
__device__ __half g_iw[NIW];
__device__ __half g_xw[NXW];
__device__ __half g_dw[NDW];
__device__ __half g_ow[NOW];

// ---------------- helpers ----------------
__device__ __forceinline__ float ex2f(float x){
    float r; asm("ex2.approx.ftz.f32 %0, %1;" : "=f"(r) : "f"(x)); return r;
}
__device__ __forceinline__ float softplusf(float x){
    if (x > 20.f) return x;
    return log1pf(__expf(x));
}
__device__ __forceinline__ void ldsm4(uint32_t r[4], uint32_t saddr){
    asm volatile("ldmatrix.sync.aligned.m8n8.x4.shared.b16 {%0,%1,%2,%3}, [%4];"
        : "=r"(r[0]),"=r"(r[1]),"=r"(r[2]),"=r"(r[3]) : "r"(saddr));
}
__device__ __forceinline__ void mma16816(float c[4], const uint32_t a[4], uint32_t b0, uint32_t b1){
    asm volatile("mma.sync.aligned.m16n8k16.row.col.f32.f16.f16.f32 "
        "{%0,%1,%2,%3}, {%4,%5,%6,%7}, {%8,%9}, {%0,%1,%2,%3};"
        : "+f"(c[0]),"+f"(c[1]),"+f"(c[2]),"+f"(c[3])
        : "r"(a[0]),"r"(a[1]),"r"(a[2]),"r"(a[3]), "r"(b0),"r"(b1));
}
__device__ __forceinline__ void cpa16(uint32_t dst, const void* src, int sz){
    asm volatile("cp.async.cg.shared.global [%0], [%1], 16, %2;"
        :: "r"(dst), "l"(src), "r"(sz));
}
#define CP_COMMIT() asm volatile("cp.async.commit_group;")
#define CP_WAIT1()  asm volatile("cp.async.wait_group 1;")

// ---------------- mask + fp16 round ----------------
__global__ void mask_kernel(const float* __restrict__ x, const float* __restrict__ m){
    int idx = blockIdx.x*256 + threadIdx.x;
    if (idx >= CBTDM) return;
    float v = x[idx] * m[idx / CDM];
    g_x[idx]  = v;
    g_xa[idx] = __float2half_rn(v);
}

// ---------------- fused weight convert ----------------
__global__ void wconv_all(const float* __restrict__ iw, const float* __restrict__ xw,
                          const float* __restrict__ dtw, const float* __restrict__ ow){
    int idx = blockIdx.x*256 + threadIdx.x;
    if (idx < NIW){ g_iw[idx] = __float2half_rn(iw[idx]); return; }
    idx -= NIW;
    if (idx < NXW){ g_xw[idx] = __float2half_rn(xw[idx]); return; }
    idx -= NXW;
    if (idx < NDW){ g_dw[idx] = __float2half_rn(dtw[idx]); return; }
    idx -= NDW;
    if (idx < NOW){ g_ow[idx] = __float2half_rn(ow[idx]); }
}

// ---------------- pipelined fp16 tensor-core GEMM (single pass, BK=64) ----------------
// 128x128 tile, BK=64, 256 threads, 3-stage cp.async ring, 1 sync/slab, 2 CTAs/SM.
// EPI: 0 plain, 1 softplus(acc+bias[n]), 2 plain + dt fp16 plane (cols<CR)
template<int EPI, typename OutT>
__global__ void __launch_bounds__(256, 2) gemm_f16(
    const __half* __restrict__ A, int lda,
    const __half* __restrict__ B, int ldb,
    OutT* __restrict__ C, int ldc,
    int M, int N, int K, const float* __restrict__ bias)
{
    constexpr int LDS = 72;                 // halves per smem row (144B; phase-conflict-free)
    constexpr int PLANE = 128*LDS;          // 9216 halves
    constexpr int STAGE = 2*PLANE;          // A | B
    extern __shared__ __align__(16) uint16_t smem[];   // [3 stages][STAGE]

    const int tid  = threadIdx.x;
    const int bm   = blockIdx.y << 7;
    const int bn   = blockIdx.x << 7;
    const int lane = tid & 31;
    const int warp = tid >> 5;
    const int wm   = (warp >> 1) << 5;
    const int wn   = (warp & 1) << 6;

    float c[2][8][4];
    #pragma unroll
    for (int i=0;i<2;i++) for (int j=0;j<8;j++) for (int k=0;k<4;k++) c[i][j][k]=0.f;

    const int nk = (K + 63) >> 6;

    auto issue_copy = [&](int it){
        int s  = it % 3;
        int k0 = it << 6;
        #pragma unroll
        for (int i=0;i<8;i++){
            int idx = i*256 + tid;            // 0..2047
            int p   = idx >> 10;              // 0:A 1:B
            int rem = idx & 1023;
            int row = rem >> 3;
            int ch  = rem & 7;
            int kk  = k0 + ch*8;
            uint16_t* dst = smem + s*STAGE + p*PLANE + row*LDS + ch*8;
            uint32_t d = (uint32_t)__cvta_generic_to_shared(dst);
            const __half* base;
            int ld, grow; bool okr;
            if (p == 0){ base = A; ld = lda; grow = bm + row; okr = true; }
            else       { base = B; ld = ldb; grow = bn + row; okr = (grow < N); }
            bool ok = okr && (kk < K);
            const __half* src = ok ? (base + (size_t)grow*ld + kk) : base;
            cpa16(d, src, ok ? 16 : 0);
        }
        CP_COMMIT();
    };

    issue_copy(0);
    if (nk > 1) issue_copy(1); else CP_COMMIT();

    for (int it = 0; it < nk; it++){
        CP_WAIT1();
        __syncthreads();

        const int s = it % 3;
        const uint16_t* pA = smem + s*STAGE;
        const uint16_t* pB = pA + PLANE;

        #pragma unroll
        for (int ks = 0; ks < 4; ks++){
            uint32_t af[2][4];
            int arow = (lane & 7) + ((lane >> 3) & 1) * 8;
            int akc  = ks*16 + ((lane & 16) ? 8 : 0);
            #pragma unroll
            for (int mf=0; mf<2; mf++)
                ldsm4(af[mf], (uint32_t)__cvta_generic_to_shared(
                    &pA[(wm + mf*16 + arow)*LDS + akc]));

            int bgrp = lane >> 3;
            int brow = (lane & 7) + ((bgrp >= 2) ? 8 : 0);
            int bkc  = ks*16 + ((bgrp & 1) ? 8 : 0);

            uint32_t bfr[8][2];
            #pragma unroll
            for (int p=0; p<4; p++){
                uint32_t r4[4];
                ldsm4(r4, (uint32_t)__cvta_generic_to_shared(
                    &pB[(wn + p*16 + brow)*LDS + bkc]));
                bfr[2*p  ][0]=r4[0]; bfr[2*p  ][1]=r4[1];
                bfr[2*p+1][0]=r4[2]; bfr[2*p+1][1]=r4[3];
            }
            #pragma unroll
            for (int mf=0; mf<2; mf++)
                #pragma unroll
                for (int nf=0; nf<8; nf++)
                    mma16816(c[mf][nf], af[mf], bfr[nf][0], bfr[nf][1]);
        }

        // slot (it+2)%3 was last read at iteration it-1; sync above covers it.
        if (it + 2 < nk) issue_copy(it + 2);
        else             CP_COMMIT();
    }

    // ---- epilogue ----
    #pragma unroll
    for (int mf=0; mf<2; mf++){
        int r0 = bm + wm + mf*16 + (lane >> 2);
        #pragma unroll
        for (int nf=0; nf<8; nf++){
            int cc = bn + wn + nf*8 + (lane & 3)*2;
            float v0 = c[mf][nf][0], v1 = c[mf][nf][1];
            float v2 = c[mf][nf][2], v3 = c[mf][nf][3];
            if (EPI == 1){
                if (cc   < N){ v0 = softplusf(v0 + bias[cc]);   v2 = softplusf(v2 + bias[cc]); }
                if (cc+1 < N){ v1 = softplusf(v1 + bias[cc+1]); v3 = softplusf(v3 + bias[cc+1]); }
            }
            if (cc + 1 < N){
                if constexpr (sizeof(OutT) == 2){
                    *(__half2*)&C[(size_t)r0*ldc + cc] =
                        __halves2half2(__float2half_rn(v0), __float2half_rn(v1));
                    *(__half2*)&C[(size_t)(r0+8)*ldc + cc] =
                        __halves2half2(__float2half_rn(v2), __float2half_rn(v3));
                } else {
                    *(float2*)&C[(size_t)r0*ldc + cc]     = make_float2(v0, v1);
                    *(float2*)&C[(size_t)(r0+8)*ldc + cc] = make_float2(v2, v3);
                }
            } else if (cc < N){
                C[(size_t)r0*ldc + cc]     = (OutT)v0;
                C[(size_t)(r0+8)*ldc + cc] = (OutT)v2;
            }
            if (EPI == 2){
                if (cc < CR){
                    g_dta[(size_t)r0*CR + cc]     = __float2half_rn(v0);
                    g_dta[(size_t)(r0+8)*CR + cc] = __float2half_rn(v2);
                }
                if (cc + 1 < CR){
                    g_dta[(size_t)r0*CR + cc+1]     = __float2half_rn(v1);
                    g_dta[(size_t)(r0+8)*CR + cc+1] = __float2half_rn(v3);
                }
            }
        }
    }
}

// ---------------- depthwise causal conv (DC=4) + SiLU (fp16 in) ----------------
__global__ void conv_silu_kernel(const float* __restrict__ cw, const float* __restrict__ cb){
    int idx = blockIdx.x*256 + threadIdx.x;
    if (idx >= CBTDI) return;
    int d  = idx % CDI;
    int bt = idx / CDI;
    int t  = bt % CT;
    const __half* up = g_xza + (size_t)(bt - t)*(2*CDI) + d;
    float w0 = cw[d*4+0], w1 = cw[d*4+1], w2 = cw[d*4+2], w3 = cw[d*4+3];
    float acc = cb[d];
    acc += w3 * __half2float(up[(size_t)t*(2*CDI)]);
    if (t >= 1) acc += w2 * __half2float(up[(size_t)(t-1)*(2*CDI)]);
    if (t >= 2) acc += w1 * __half2float(up[(size_t)(t-2)*(2*CDI)]);
    if (t >= 3) acc += w0 * __half2float(up[(size_t)(t-3)*(2*CDI)]);
    float s = 1.f/(1.f + __expf(-acc));
    float v = acc * s;
    g_uc[idx]  = v;
    g_uca[idx] = __float2half_rn(v);
}

// ---------------- selective scan (round-9 structure; z from fp16) ----------------
__global__ void __launch_bounds__(128) scan_kernel(
    const float* __restrict__ alog,
    const float* __restrict__ Dp)
{
    __shared__ float sB[64][64];
    __shared__ float sC[64][64];
    __shared__ float sdel[64][16];
    __shared__ float su  [64][16];
    __shared__ float sz  [64][16];

    const int b     = blockIdx.y;
    const int dbase = blockIdx.x * 16;
    const int tid   = threadIdx.x;
    const int lane  = tid & 31;
    const int warp  = tid >> 5;
    const int g = lane >> 3, q = lane & 7;
    const int dl = warp*4 + g;
    const int d  = dbase + dl;

    float h[8], aa[8];
    #pragma unroll
    for (int j=0;j<8;j++){
        h[j]  = 0.f;
        aa[j] = -__expf(alog[d*CN + q*8 + j]) * LOG2E_F;
    }
    const float Dd = Dp[d];

    const float step = (aa[7] - aa[0]) * (1.f/7.f);
    float amax = fmaxf(fabsf(aa[0]), fabsf(aa[7]));
    bool geo = true;
    #pragma unroll
    for (int j=0;j<8;j++)
        geo = geo && (fabsf(aa[j] - (aa[0] + j*step)) <= 1e-4f*amax + 1e-7f);
    geo = __all_sync(0xffffffffu, geo);
    const float aa0 = aa[0];

    for (int t0 = 0; t0 < CT; t0 += 64){
        const size_t rowbase = (size_t)b*CT + t0;
        for (int i = tid; i < 64*128; i += 128){
            int tt = i >> 7, c = i & 127;
            float v = g_proj[(rowbase+tt)*CPW + CR + c];
            if (c < 64) sB[tt][c] = v; else sC[tt][c-64] = v;
        }
        for (int i = tid; i < 64*16; i += 128){
            int tt = i >> 4, dd = i & 15;
            size_t r = rowbase + tt;
            sdel[tt][dd] = g_del[r*CDI + dbase + dd];
            su[tt][dd]   = g_uc [r*CDI + dbase + dd];
            sz[tt][dd]   = __half2float(g_xza[r*(2*CDI) + CDI + dbase + dd]);
        }
        __syncthreads();

        if (geo){
            #pragma unroll 2
            for (int tt=0; tt<64; tt++){
                float dlt = sdel[tt][dl];
                float u   = su[tt][dl];
                float du  = dlt * u;
                float4 B0 = *(const float4*)&sB[tt][q*8];
                float4 B1 = *(const float4*)&sB[tt][q*8+4];
                float4 C0 = *(const float4*)&sC[tt][q*8];
                float4 C1 = *(const float4*)&sC[tt][q*8+4];
                float Bv[8] = {B0.x,B0.y,B0.z,B0.w,B1.x,B1.y,B1.z,B1.w};
                float Cv[8] = {C0.x,C0.y,C0.z,C0.w,C1.x,C1.y,C1.z,C1.w};
                float e0 = ex2f(dlt*aa0);
                float rr = ex2f(dlt*step);
                float rr2 = rr*rr, rr4 = rr2*rr2;
                float ev[8];
                ev[0]=e0;        ev[1]=e0*rr;
                ev[2]=ev[0]*rr2; ev[3]=ev[1]*rr2;
                ev[4]=ev[0]*rr4; ev[5]=ev[1]*rr4;
                ev[6]=ev[2]*rr4; ev[7]=ev[3]*rr4;
                float yp = 0.f;
                #pragma unroll
                for (int j=0;j<8;j++){
                    h[j] = h[j]*ev[j] + du*Bv[j];
                    yp += h[j]*Cv[j];
                }
                yp += __shfl_xor_sync(0xffffffffu, yp, 1);
                yp += __shfl_xor_sync(0xffffffffu, yp, 2);
                yp += __shfl_xor_sync(0xffffffffu, yp, 4);
                if (q == 0){
                    float z = sz[tt][dl];
                    float s = 1.f/(1.f + __expf(-z));
                    float v = (yp + u*Dd) * (z*s);
                    g_ya[(rowbase+tt)*CDI + d] = __float2half_rn(v);
                }
            }
        } else {
            #pragma unroll 2
            for (int tt=0; tt<64; tt++){
                float dlt = sdel[tt][dl];
                float u   = su[tt][dl];
                float du  = dlt * u;
                float4 B0 = *(const float4*)&sB[tt][q*8];
                float4 B1 = *(const float4*)&sB[tt][q*8+4];
                float4 C0 = *(const float4*)&sC[tt][q*8];
                float4 C1 = *(const float4*)&sC[tt][q*8+4];
                float Bv[8] = {B0.x,B0.y,B0.z,B0.w,B1.x,B1.y,B1.z,B1.w};
                float Cv[8] = {C0.x,C0.y,C0.z,C0.w,C1.x,C1.y,C1.z,C1.w};
                float yp = 0.f;
                #pragma unroll
                for (int j=0;j<8;j++){
                    h[j] = h[j]*ex2f(dlt*aa[j]) + du*Bv[j];
                    yp += h[j]*Cv[j];
                }
                yp += __shfl_xor_sync(0xffffffffu, yp, 1);
                yp += __shfl_xor_sync(0xffffffffu, yp, 2);
                yp += __shfl_xor_sync(0xffffffffu, yp, 4);
                if (q == 0){
                    float z = sz[tt][dl];
                    float s = 1.f/(1.f + __expf(-z));
                    float v = (yp + u*Dd) * (z*s);
                    g_ya[(rowbase+tt)*CDI + d] = __float2half_rn(v);
                }
            }
        }
        __syncthreads();
    }
}

// ---------------- LayerNorm + FiLM + residual ----------------
__device__ __forceinline__ float blockReduceSum(float v){
    __shared__ float sh[8];
    __shared__ float tot;
    int lane = threadIdx.x & 31, w = threadIdx.x >> 5;
    #pragma unroll
    for (int o=16;o;o>>=1) v += __shfl_down_sync(0xffffffffu, v, o);
    if (!lane) sh[w] = v;
    __syncthreads();
    v = (threadIdx.x < 8) ? sh[threadIdx.x] : 0.f;
    if (w == 0){
        #pragma unroll
        for (int o=4;o;o>>=1) v += __shfl_down_sync(0xffffffffu, v, o);
    }
    if (threadIdx.x == 0) tot = v;
    __syncthreads();
    return tot;
}

template<int SPLIT>
__global__ void __launch_bounds__(256) ln_film_res_kernel(
    const float* __restrict__ gamma, const float* __restrict__ beta,
    const float* __restrict__ w, const float* __restrict__ bln,
    float* __restrict__ out)
{
    const int row = blockIdx.x;
    const int tid = threadIdx.x;
    const size_t base = (size_t)row*CDM;
    float v0 = g_ho[base+tid], v1 = g_ho[base+tid+256], v2 = g_ho[base+tid+512];
    float mean = blockReduceSum(v0+v1+v2) * (1.f/CDM);
    float d0 = v0-mean, d1 = v1-mean, d2 = v2-mean;
    float var = blockReduceSum(d0*d0 + d1*d1 + d2*d2) * (1.f/CDM);
    float rstd = rsqrtf(var + 1e-5f);
    float dv[3] = {d0, d1, d2};
    #pragma unroll
    for (int k=0;k<3;k++){
        int c = tid + k*256;
        float o = dv[k]*rstd*w[c] + bln[c];
        float v = gamma[base+c]*o + beta[base+c] + g_x[base+c];
        out[base+c] = v;
        if (SPLIT) g_xa[base+c] = __float2half_rn(v);
    }
}

// ---------------- launch ----------------
extern "C" void kernel_launch(void* const* d_in, const int* in_sizes, int n_in,
                              void* d_out, int out_size)
{
    (void)in_sizes; (void)n_in; (void)out_size;
    const float* x     = (const float*)d_in[0];
    const float* mask  = (const float*)d_in[1];
    const float* fgam  = (const float*)d_in[2];
    const float* fbet  = (const float*)d_in[3];
    const float* in_w  = (const float*)d_in[4];
    const float* cw    = (const float*)d_in[5];
    const float* cb    = (const float*)d_in[6];
    const float* xw    = (const float*)d_in[7];
    const float* dtw   = (const float*)d_in[8];
    const float* dtb   = (const float*)d_in[9];
    const float* alog  = (const float*)d_in[10];
    const float* Dp    = (const float*)d_in[11];
    const float* ow    = (const float*)d_in[12];
    const float* lnw   = (const float*)d_in[13];
    const float* lnb   = (const float*)d_in[14];

    float *gx, *guc, *gproj, *gdel, *gho;
    cudaGetSymbolAddress((void**)&gx,   g_x);
    cudaGetSymbolAddress((void**)&guc,  g_uc);
    cudaGetSymbolAddress((void**)&gproj,g_proj);
    cudaGetSymbolAddress((void**)&gdel, g_del);
    cudaGetSymbolAddress((void**)&gho,  g_ho);

    __half *xza, *xa, *uca, *dta, *ya, *iw, *xwp, *dw, *owp;
    cudaGetSymbolAddress((void**)&xza, g_xza);
    cudaGetSymbolAddress((void**)&xa,  g_xa);
    cudaGetSymbolAddress((void**)&uca, g_uca);
    cudaGetSymbolAddress((void**)&dta, g_dta);
    cudaGetSymbolAddress((void**)&ya,  g_ya);
    cudaGetSymbolAddress((void**)&iw,  g_iw);
    cudaGetSymbolAddress((void**)&xwp, g_xw);
    cudaGetSymbolAddress((void**)&dw,  g_dw);
    cudaGetSymbolAddress((void**)&owp, g_ow);

    const int SMEM = 3*2*128*72*2;   // 110592 B dynamic smem (3 stages x 2 planes, BK=64)
    cudaFuncSetAttribute(gemm_f16<0,__half>, cudaFuncAttributeMaxDynamicSharedMemorySize, SMEM);
    cudaFuncSetAttribute(gemm_f16<1,float>,  cudaFuncAttributeMaxDynamicSharedMemorySize, SMEM);
    cudaFuncSetAttribute(gemm_f16<2,float>,  cudaFuncAttributeMaxDynamicSharedMemorySize, SMEM);
    cudaFuncSetAttribute(gemm_f16<0,float>,  cudaFuncAttributeMaxDynamicSharedMemorySize, SMEM);

    mask_kernel<<<(CBTDM + 255)/256, 256>>>(x, mask);
    {
        int n = NIW + NXW + NDW + NOW;
        wconv_all<<<(n+255)/256, 256>>>(in_w, xw, dtw, ow);
    }

    for (int l = 0; l < 2; l++){
        // xz = x @ W_in^T -> fp16  [8192 x 3072 x 768]
        gemm_f16<0,__half><<<dim3(24,64), 256, SMEM>>>(
            xa, CDM, iw + (size_t)l*NIW/2, CDM,
            xza, 2*CDI, CBT, 2*CDI, CDM, nullptr);
        // depthwise conv + silu (fp16 in, fp32+fp16 out)
        conv_silu_kernel<<<(CBTDI + 255)/256, 256>>>(cw + (size_t)l*CDI*4, cb + (size_t)l*CDI);
        // proj = u_c @ W_x^T -> fp32 (+ dt fp16 plane)  [8192 x 176 x 1536]
        gemm_f16<2,float><<<dim3(2,64), 256, SMEM>>>(
            uca, CDI, xwp + (size_t)l*NXW/2, CDI,
            gproj, CPW, CBT, CPW, CDI, nullptr);
        // delta = softplus(dt @ W_dt^T + b) -> fp32  [8192 x 1536 x 48]
        gemm_f16<1,float><<<dim3(12,64), 256, SMEM>>>(
            dta, CR, dw + (size_t)l*NDW/2, CR,
            gdel, CDI, CBT, CDI, CR, dtb + (size_t)l*CDI);
        // selective scan -> fp16 y
        scan_kernel<<<dim3(CDI/16, CB), 128>>>(alog + (size_t)l*CDI*CN, Dp + (size_t)l*CDI);
        // h_out = y @ W_out^T -> fp32  [8192 x 768 x 1536]
        gemm_f16<0,float><<<dim3(6,64), 256, SMEM>>>(
            ya, CDI, owp + (size_t)l*NOW/2, CDI,
            gho, CDM, CBT, CDM, CDI, nullptr);
        // LN + FiLM + residual
        if (l == 0)
            ln_film_res_kernel<1><<<CBT, 256>>>(fgam, fbet, lnw, lnb, gx);
        else
            ln_film_res_kernel<0><<<CBT, 256>>>(fgam + (size_t)CBTDM, fbet + (size_t)CBTDM,
                                                lnw + CDM, lnb + CDM, (float*)d_out);
    }
}

// round 13
// speedup vs baseline: 1.5454x; 1.5454x over previous
#include <cuda_runtime.h>
#include <cuda_fp16.h>
#include <math.h>
#include <stdint.h>

// ---------------- problem constants ----------------
constexpr int CB  = 4;
constexpr int CT  = 2048;
constexpr int CDM = 768;
constexpr int CDI = 1536;
constexpr int CN  = 64;
constexpr int CR  = 48;
constexpr int CPW = CR + 2*CN;      // 176
constexpr int CBT   = CB*CT;        // 8192
constexpr int CBTDM = CBT*CDM;
constexpr int CBTDI = CBT*CDI;

constexpr int NIW = 2*2*CDI*CDM;
constexpr int NXW = 2*CPW*CDI;
constexpr int NDW = 2*CDI*CR;
constexpr int NOW = 2*CDM*CDI;

#define LOG2E_F 1.4426950408889634f

// ---------------- fp32 scratch ----------------
__device__ float g_x   [CBTDM];
__device__ float g_proj[CBT*CPW];
__device__ float g_ho  [CBTDM];

// ---------------- fp16 planes ----------------
__device__ __half g_xza[CBT*2*CDI];   // in_proj output (u|z)
__device__ __half g_xa [CBTDM];
__device__ __half g_uca[CBTDI];       // conv+silu out
__device__ __half g_del[CBTDI];       // delta
__device__ __half g_dta[CBT*CR];
__device__ __half g_ya [CBTDI];
// fp16 weights
__device__ __half g_iw[NIW];
__device__ __half g_xw[NXW];
__device__ __half g_dw[NDW];
__device__ __half g_ow[NOW];

// ---------------- helpers ----------------
__device__ __forceinline__ float ex2f(float x){
    float r; asm("ex2.approx.ftz.f32 %0, %1;" : "=f"(r) : "f"(x)); return r;
}
__device__ __forceinline__ float softplusf(float x){
    if (x > 20.f) return x;
    return log1pf(__expf(x));
}
__device__ __forceinline__ void ldsm4(uint32_t r[4], uint32_t saddr){
    asm volatile("ldmatrix.sync.aligned.m8n8.x4.shared.b16 {%0,%1,%2,%3}, [%4];"
        : "=r"(r[0]),"=r"(r[1]),"=r"(r[2]),"=r"(r[3]) : "r"(saddr));
}
__device__ __forceinline__ void mma16816(float c[4], const uint32_t a[4], uint32_t b0, uint32_t b1){
    asm volatile("mma.sync.aligned.m16n8k16.row.col.f32.f16.f16.f32 "
        "{%0,%1,%2,%3}, {%4,%5,%6,%7}, {%8,%9}, {%0,%1,%2,%3};"
        : "+f"(c[0]),"+f"(c[1]),"+f"(c[2]),"+f"(c[3])
        : "r"(a[0]),"r"(a[1]),"r"(a[2]),"r"(a[3]), "r"(b0),"r"(b1));
}
__device__ __forceinline__ void cpa16(uint32_t dst, const void* src, int sz){
    asm volatile("cp.async.cg.shared.global [%0], [%1], 16, %2;"
        :: "r"(dst), "l"(src), "r"(sz));
}
#define CP_COMMIT() asm volatile("cp.async.commit_group;")
#define CP_WAIT1()  asm volatile("cp.async.wait_group 1;")

// ---------------- mask + fp16 round ----------------
__global__ void mask_kernel(const float* __restrict__ x, const float* __restrict__ m){
    int idx = blockIdx.x*256 + threadIdx.x;
    if (idx >= CBTDM) return;
    float v = x[idx] * m[idx / CDM];
    g_x[idx]  = v;
    g_xa[idx] = __float2half_rn(v);
}

// ---------------- fused weight convert ----------------
__global__ void wconv_all(const float* __restrict__ iw, const float* __restrict__ xw,
                          const float* __restrict__ dtw, const float* __restrict__ ow){
    int idx = blockIdx.x*256 + threadIdx.x;
    if (idx < NIW){ g_iw[idx] = __float2half_rn(iw[idx]); return; }
    idx -= NIW;
    if (idx < NXW){ g_xw[idx] = __float2half_rn(xw[idx]); return; }
    idx -= NXW;
    if (idx < NDW){ g_dw[idx] = __float2half_rn(dtw[idx]); return; }
    idx -= NDW;
    if (idx < NOW){ g_ow[idx] = __float2half_rn(ow[idx]); }
}

// ---------------- pipelined fp16 tensor-core GEMM (single pass, BK=32) ----------------
// 128x128 tile, 256 threads, 3-stage cp.async ring, 1 sync/slab, 2 CTAs/SM.
// EPI: 0 plain, 1 softplus(acc+bias[n]), 2 plain + dt fp16 plane (cols<CR)
template<int EPI, typename OutT>
__global__ void __launch_bounds__(256, 2) gemm_f16(
    const __half* __restrict__ A, int lda,
    const __half* __restrict__ B, int ldb,
    OutT* __restrict__ C, int ldc,
    int M, int N, int K, const float* __restrict__ bias)
{
    constexpr int LDS = 40;                 // halves per smem row (80B)
    constexpr int PLANE = 128*LDS;          // 5120 halves
    constexpr int STAGE = 2*PLANE;          // A | B
    extern __shared__ __align__(16) uint16_t smem[];   // [3 stages][STAGE]

    const int tid  = threadIdx.x;
    const int bm   = blockIdx.y << 7;
    const int bn   = blockIdx.x << 7;
    const int lane = tid & 31;
    const int warp = tid >> 5;
    const int wm   = (warp >> 1) << 5;
    const int wn   = (warp & 1) << 6;

    float c[2][8][4];
    #pragma unroll
    for (int i=0;i<2;i++) for (int j=0;j<8;j++) for (int k=0;k<4;k++) c[i][j][k]=0.f;

    const int nk = (K + 31) >> 5;

    auto issue_copy = [&](int it){
        int s  = it % 3;
        int k0 = it << 5;
        #pragma unroll
        for (int i=0;i<4;i++){
            int idx = i*256 + tid;            // 0..1023
            int p   = idx >> 9;               // 0:A 1:B
            int rem = idx & 511;
            int row = rem >> 2;
            int ch  = rem & 3;
            int kk  = k0 + ch*8;
            uint16_t* dst = smem + s*STAGE + p*PLANE + row*LDS + ch*8;
            uint32_t d = (uint32_t)__cvta_generic_to_shared(dst);
            const __half* base;
            int ld, grow; bool okr;
            if (p == 0){ base = A; ld = lda; grow = bm + row; okr = true; }
            else       { base = B; ld = ldb; grow = bn + row; okr = (grow < N); }
            bool ok = okr && (kk < K);
            const __half* src = ok ? (base + (size_t)grow*ld + kk) : base;
            cpa16(d, src, ok ? 16 : 0);
        }
        CP_COMMIT();
    };

    issue_copy(0);
    if (nk > 1) issue_copy(1); else CP_COMMIT();

    for (int it = 0; it < nk; it++){
        CP_WAIT1();
        __syncthreads();

        const int s = it % 3;
        const uint16_t* pA = smem + s*STAGE;
        const uint16_t* pB = pA + PLANE;

        #pragma unroll
        for (int ks = 0; ks < 2; ks++){
            uint32_t af[2][4];
            int arow = (lane & 7) + ((lane >> 3) & 1) * 8;
            int akc  = ks*16 + ((lane & 16) ? 8 : 0);
            #pragma unroll
            for (int mf=0; mf<2; mf++)
                ldsm4(af[mf], (uint32_t)__cvta_generic_to_shared(
                    &pA[(wm + mf*16 + arow)*LDS + akc]));

            int bgrp = lane >> 3;
            int brow = (lane & 7) + ((bgrp >= 2) ? 8 : 0);
            int bkc  = ks*16 + ((bgrp & 1) ? 8 : 0);

            uint32_t bfr[8][2];
            #pragma unroll
            for (int p=0; p<4; p++){
                uint32_t r4[4];
                ldsm4(r4, (uint32_t)__cvta_generic_to_shared(
                    &pB[(wn + p*16 + brow)*LDS + bkc]));
                bfr[2*p  ][0]=r4[0]; bfr[2*p  ][1]=r4[1];
                bfr[2*p+1][0]=r4[2]; bfr[2*p+1][1]=r4[3];
            }
            #pragma unroll
            for (int mf=0; mf<2; mf++)
                #pragma unroll
                for (int nf=0; nf<8; nf++)
                    mma16816(c[mf][nf], af[mf], bfr[nf][0], bfr[nf][1]);
        }

        // slot (it+2)%3 was last read at iteration it-1; sync above covers it.
        if (it + 2 < nk) issue_copy(it + 2);
        else             CP_COMMIT();
    }

    // ---- epilogue ----
    #pragma unroll
    for (int mf=0; mf<2; mf++){
        int r0 = bm + wm + mf*16 + (lane >> 2);
        #pragma unroll
        for (int nf=0; nf<8; nf++){
            int cc = bn + wn + nf*8 + (lane & 3)*2;
            float v0 = c[mf][nf][0], v1 = c[mf][nf][1];
            float v2 = c[mf][nf][2], v3 = c[mf][nf][3];
            if (EPI == 1){
                if (cc   < N){ v0 = softplusf(v0 + bias[cc]);   v2 = softplusf(v2 + bias[cc]); }
                if (cc+1 < N){ v1 = softplusf(v1 + bias[cc+1]); v3 = softplusf(v3 + bias[cc+1]); }
            }
            if (cc + 1 < N){
                if constexpr (sizeof(OutT) == 2){
                    *(__half2*)&C[(size_t)r0*ldc + cc] =
                        __halves2half2(__float2half_rn(v0), __float2half_rn(v1));
                    *(__half2*)&C[(size_t)(r0+8)*ldc + cc] =
                        __halves2half2(__float2half_rn(v2), __float2half_rn(v3));
                } else {
                    *(float2*)&C[(size_t)r0*ldc + cc]     = make_float2(v0, v1);
                    *(float2*)&C[(size_t)(r0+8)*ldc + cc] = make_float2(v2, v3);
                }
            } else if (cc < N){
                C[(size_t)r0*ldc + cc]     = (OutT)v0;
                C[(size_t)(r0+8)*ldc + cc] = (OutT)v2;
            }
            if (EPI == 2){
                if (cc < CR){
                    g_dta[(size_t)r0*CR + cc]     = __float2half_rn(v0);
                    g_dta[(size_t)(r0+8)*CR + cc] = __float2half_rn(v2);
                }
                if (cc + 1 < CR){
                    g_dta[(size_t)r0*CR + cc+1]     = __float2half_rn(v1);
                    g_dta[(size_t)(r0+8)*CR + cc+1] = __float2half_rn(v3);
                }
            }
        }
    }
}

// ---------------- depthwise causal conv (DC=4) + SiLU, half2-vectorized ----------------
__global__ void conv_silu_kernel(const float* __restrict__ cw, const float* __restrict__ cb){
    int idx = blockIdx.x*256 + threadIdx.x;
    if (idx >= CBTDI/2) return;
    int d2 = idx % (CDI/2);
    int bt = idx / (CDI/2);
    int t  = bt % CT;
    int d  = d2*2;
    // g_xza row = 2*CDI halves = CDI half2; u occupies first CDI/2 half2 of each row
    const __half2* row0 = reinterpret_cast<const __half2*>(g_xza + (size_t)(bt - t)*(2*CDI));
    float acc0 = cb[d], acc1 = cb[d+1];
    {
        float2 v = __half22float2(row0[(size_t)t*CDI + d2]);
        acc0 += cw[d*4+3]*v.x; acc1 += cw[(d+1)*4+3]*v.y;
    }
    if (t >= 1){
        float2 v = __half22float2(row0[(size_t)(t-1)*CDI + d2]);
        acc0 += cw[d*4+2]*v.x; acc1 += cw[(d+1)*4+2]*v.y;
    }
    if (t >= 2){
        float2 v = __half22float2(row0[(size_t)(t-2)*CDI + d2]);
        acc0 += cw[d*4+1]*v.x; acc1 += cw[(d+1)*4+1]*v.y;
    }
    if (t >= 3){
        float2 v = __half22float2(row0[(size_t)(t-3)*CDI + d2]);
        acc0 += cw[d*4+0]*v.x; acc1 += cw[(d+1)*4+0]*v.y;
    }
    float s0 = acc0 / (1.f + __expf(-acc0));
    float s1 = acc1 / (1.f + __expf(-acc1));
    reinterpret_cast<__half2*>(g_uca)[(size_t)bt*(CDI/2) + d2] =
        __halves2half2(__float2half_rn(s0), __float2half_rn(s1));
}

// ---------------- selective scan (R11 structure; fp16 delta/u/z inputs) ----------------
__global__ void __launch_bounds__(128) scan_kernel(
    const float* __restrict__ alog,
    const float* __restrict__ Dp)
{
    __shared__ float sB[64][64];
    __shared__ float sC[64][64];
    __shared__ float sdel[64][16];
    __shared__ float su  [64][16];
    __shared__ float sz  [64][16];

    const int b     = blockIdx.y;
    const int dbase = blockIdx.x * 16;
    const int tid   = threadIdx.x;
    const int lane  = tid & 31;
    const int warp  = tid >> 5;
    const int g = lane >> 3, q = lane & 7;
    const int dl = warp*4 + g;
    const int d  = dbase + dl;

    float h[8], aa[8];
    #pragma unroll
    for (int j=0;j<8;j++){
        h[j]  = 0.f;
        aa[j] = -__expf(alog[d*CN + q*8 + j]) * LOG2E_F;
    }
    const float Dd = Dp[d];

    const float step = (aa[7] - aa[0]) * (1.f/7.f);
    float amax = fmaxf(fabsf(aa[0]), fabsf(aa[7]));
    bool geo = true;
    #pragma unroll
    for (int j=0;j<8;j++)
        geo = geo && (fabsf(aa[j] - (aa[0] + j*step)) <= 1e-4f*amax + 1e-7f);
    geo = __all_sync(0xffffffffu, geo);
    const float aa0 = aa[0];

    for (int t0 = 0; t0 < CT; t0 += 64){
        const size_t rowbase = (size_t)b*CT + t0;
        for (int i = tid; i < 64*128; i += 128){
            int tt = i >> 7, c = i & 127;
            float v = g_proj[(rowbase+tt)*CPW + CR + c];
            if (c < 64) sB[tt][c] = v; else sC[tt][c-64] = v;
        }
        for (int i = tid; i < 64*16; i += 128){
            int tt = i >> 4, dd = i & 15;
            size_t r = rowbase + tt;
            sdel[tt][dd] = __half2float(g_del[r*CDI + dbase + dd]);
            su[tt][dd]   = __half2float(g_uca[r*CDI + dbase + dd]);
            sz[tt][dd]   = __half2float(g_xza[r*(2*CDI) + CDI + dbase + dd]);
        }
        __syncthreads();

        if (geo){
            #pragma unroll 2
            for (int tt=0; tt<64; tt++){
                float dlt = sdel[tt][dl];
                float u   = su[tt][dl];
                float du  = dlt * u;
                float4 B0 = *(const float4*)&sB[tt][q*8];
                float4 B1 = *(const float4*)&sB[tt][q*8+4];
                float4 C0 = *(const float4*)&sC[tt][q*8];
                float4 C1 = *(const float4*)&sC[tt][q*8+4];
                float Bv[8] = {B0.x,B0.y,B0.z,B0.w,B1.x,B1.y,B1.z,B1.w};
                float Cv[8] = {C0.x,C0.y,C0.z,C0.w,C1.x,C1.y,C1.z,C1.w};
                float e0 = ex2f(dlt*aa0);
                float rr = ex2f(dlt*step);
                float rr2 = rr*rr, rr4 = rr2*rr2;
                float ev[8];
                ev[0]=e0;        ev[1]=e0*rr;
                ev[2]=ev[0]*rr2; ev[3]=ev[1]*rr2;
                ev[4]=ev[0]*rr4; ev[5]=ev[1]*rr4;
                ev[6]=ev[2]*rr4; ev[7]=ev[3]*rr4;
                float yp = 0.f;
                #pragma unroll
                for (int j=0;j<8;j++){
                    h[j] = h[j]*ev[j] + du*Bv[j];
                    yp += h[j]*Cv[j];
                }
                yp += __shfl_xor_sync(0xffffffffu, yp, 1);
                yp += __shfl_xor_sync(0xffffffffu, yp, 2);
                yp += __shfl_xor_sync(0xffffffffu, yp, 4);
                if (q == 0){
                    float z = sz[tt][dl];
                    float s = 1.f/(1.f + __expf(-z));
                    float v = (yp + u*Dd) * (z*s);
                    g_ya[(rowbase+tt)*CDI + d] = __float2half_rn(v);
                }
            }
        } else {
            #pragma unroll 2
            for (int tt=0; tt<64; tt++){
                float dlt = sdel[tt][dl];
                float u   = su[tt][dl];
                float du  = dlt * u;
                float4 B0 = *(const float4*)&sB[tt][q*8];
                float4 B1 = *(const float4*)&sB[tt][q*8+4];
                float4 C0 = *(const float4*)&sC[tt][q*8];
                float4 C1 = *(const float4*)&sC[tt][q*8+4];
                float Bv[8] = {B0.x,B0.y,B0.z,B0.w,B1.x,B1.y,B1.z,B1.w};
                float Cv[8] = {C0.x,C0.y,C0.z,C0.w,C1.x,C1.y,C1.z,C1.w};
                float yp = 0.f;
                #pragma unroll
                for (int j=0;j<8;j++){
                    h[j] = h[j]*ex2f(dlt*aa[j]) + du*Bv[j];
                    yp += h[j]*Cv[j];
                }
                yp += __shfl_xor_sync(0xffffffffu, yp, 1);
                yp += __shfl_xor_sync(0xffffffffu, yp, 2);
                yp += __shfl_xor_sync(0xffffffffu, yp, 4);
                if (q == 0){
                    float z = sz[tt][dl];
                    float s = 1.f/(1.f + __expf(-z));
                    float v = (yp + u*Dd) * (z*s);
                    g_ya[(rowbase+tt)*CDI + d] = __float2half_rn(v);
                }
            }
        }
        __syncthreads();
    }
}

// ---------------- LayerNorm + FiLM + residual ----------------
__device__ __forceinline__ float blockReduceSum(float v){
    __shared__ float sh[8];
    __shared__ float tot;
    int lane = threadIdx.x & 31, w = threadIdx.x >> 5;
    #pragma unroll
    for (int o=16;o;o>>=1) v += __shfl_down_sync(0xffffffffu, v, o);
    if (!lane) sh[w] = v;
    __syncthreads();
    v = (threadIdx.x < 8) ? sh[threadIdx.x] : 0.f;
    if (w == 0){
        #pragma unroll
        for (int o=4;o;o>>=1) v += __shfl_down_sync(0xffffffffu, v, o);
    }
    if (threadIdx.x == 0) tot = v;
    __syncthreads();
    return tot;
}

template<int SPLIT>
__global__ void __launch_bounds__(256) ln_film_res_kernel(
    const float* __restrict__ gamma, const float* __restrict__ beta,
    const float* __restrict__ w, const float* __restrict__ bln,
    float* __restrict__ out)
{
    const int row = blockIdx.x;
    const int tid = threadIdx.x;
    const size_t base = (size_t)row*CDM;
    float v0 = g_ho[base+tid], v1 = g_ho[base+tid+256], v2 = g_ho[base+tid+512];
    float mean = blockReduceSum(v0+v1+v2) * (1.f/CDM);
    float d0 = v0-mean, d1 = v1-mean, d2 = v2-mean;
    float var = blockReduceSum(d0*d0 + d1*d1 + d2*d2) * (1.f/CDM);
    float rstd = rsqrtf(var + 1e-5f);
    float dv[3] = {d0, d1, d2};
    #pragma unroll
    for (int k=0;k<3;k++){
        int c = tid + k*256;
        float o = dv[k]*rstd*w[c] + bln[c];
        float v = gamma[base+c]*o + beta[base+c] + g_x[base+c];
        out[base+c] = v;
        if (SPLIT) g_xa[base+c] = __float2half_rn(v);
    }
}

// ---------------- launch ----------------
extern "C" void kernel_launch(void* const* d_in, const int* in_sizes, int n_in,
                              void* d_out, int out_size)
{
    (void)in_sizes; (void)n_in; (void)out_size;
    const float* x     = (const float*)d_in[0];
    const float* mask  = (const float*)d_in[1];
    const float* fgam  = (const float*)d_in[2];
    const float* fbet  = (const float*)d_in[3];
    const float* in_w  = (const float*)d_in[4];
    const float* cw    = (const float*)d_in[5];
    const float* cb    = (const float*)d_in[6];
    const float* xw    = (const float*)d_in[7];
    const float* dtw   = (const float*)d_in[8];
    const float* dtb   = (const float*)d_in[9];
    const float* alog  = (const float*)d_in[10];
    const float* Dp    = (const float*)d_in[11];
    const float* ow    = (const float*)d_in[12];
    const float* lnw   = (const float*)d_in[13];
    const float* lnb   = (const float*)d_in[14];

    float *gx, *gproj, *gho;
    cudaGetSymbolAddress((void**)&gx,   g_x);
    cudaGetSymbolAddress((void**)&gproj,g_proj);
    cudaGetSymbolAddress((void**)&gho,  g_ho);

    __half *xza, *xa, *uca, *dela, *dta, *ya, *iw, *xwp, *dw, *owp;
    cudaGetSymbolAddress((void**)&xza,  g_xza);
    cudaGetSymbolAddress((void**)&xa,   g_xa);
    cudaGetSymbolAddress((void**)&uca,  g_uca);
    cudaGetSymbolAddress((void**)&dela, g_del);
    cudaGetSymbolAddress((void**)&dta,  g_dta);
    cudaGetSymbolAddress((void**)&ya,   g_ya);
    cudaGetSymbolAddress((void**)&iw,   g_iw);
    cudaGetSymbolAddress((void**)&xwp,  g_xw);
    cudaGetSymbolAddress((void**)&dw,   g_dw);
    cudaGetSymbolAddress((void**)&owp,  g_ow);

    const int SMEM = 3*2*128*40*2;   // 61440 B dynamic smem (3 stages x 2 planes, BK=32)
    cudaFuncSetAttribute(gemm_f16<0,__half>, cudaFuncAttributeMaxDynamicSharedMemorySize, SMEM);
    cudaFuncSetAttribute(gemm_f16<1,__half>, cudaFuncAttributeMaxDynamicSharedMemorySize, SMEM);
    cudaFuncSetAttribute(gemm_f16<2,float>,  cudaFuncAttributeMaxDynamicSharedMemorySize, SMEM);
    cudaFuncSetAttribute(gemm_f16<0,float>,  cudaFuncAttributeMaxDynamicSharedMemorySize, SMEM);

    mask_kernel<<<(CBTDM + 255)/256, 256>>>(x, mask);
    {
        int n = NIW + NXW + NDW + NOW;
        wconv_all<<<(n+255)/256, 256>>>(in_w, xw, dtw, ow);
    }

    for (int l = 0; l < 2; l++){
        // xz = x @ W_in^T -> fp16  [8192 x 3072 x 768]
        gemm_f16<0,__half><<<dim3(24,64), 256, SMEM>>>(
            xa, CDM, iw + (size_t)l*NIW/2, CDM,
            xza, 2*CDI, CBT, 2*CDI, CDM, nullptr);
        // depthwise conv + silu (half2 vectorized, fp16 out)
        conv_silu_kernel<<<(CBTDI/2 + 255)/256, 256>>>(cw + (size_t)l*CDI*4, cb + (size_t)l*CDI);
        // proj = u_c @ W_x^T -> fp32 (+ dt fp16 plane)  [8192 x 176 x 1536]
        gemm_f16<2,float><<<dim3(2,64), 256, SMEM>>>(
            uca, CDI, xwp + (size_t)l*NXW/2, CDI,
            gproj, CPW, CBT, CPW, CDI, nullptr);
        // delta = softplus(dt @ W_dt^T + b) -> fp16  [8192 x 1536 x 48]
        gemm_f16<1,__half><<<dim3(12,64), 256, SMEM>>>(
            dta, CR, dw + (size_t)l*NDW/2, CR,
            dela, CDI, CBT, CDI, CR, dtb + (size_t)l*CDI);
        // selective scan -> fp16 y
        scan_kernel<<<dim3(CDI/16, CB), 128>>>(alog + (size_t)l*CDI*CN, Dp + (size_t)l*CDI);
        // h_out = y @ W_out^T -> fp32  [8192 x 768 x 1536]
        gemm_f16<0,float><<<dim3(6,64), 256, SMEM>>>(
            ya, CDI, owp + (size_t)l*NOW/2, CDI,
            gho, CDM, CBT, CDM, CDI, nullptr);
        // LN + FiLM + residual
        if (l == 0)
            ln_film_res_kernel<1><<<CBT, 256>>>(fgam, fbet, lnw, lnb, gx);
        else
            ln_film_res_kernel<0><<<CBT, 256>>>(fgam + (size_t)CBTDM, fbet + (size_t)CBTDM,
                                                lnw + CDM, lnb + CDM, (float*)d_out);
    }
}

// round 14
// speedup vs baseline: 1.5701x; 1.0160x over previous
#include <cuda_runtime.h>
#include <cuda_fp16.h>
#include <math.h>
#include <stdint.h>

// ---------------- problem constants ----------------
constexpr int CB  = 4;
constexpr int CT  = 2048;
constexpr int CDM = 768;
constexpr int CDI = 1536;
constexpr int CN  = 64;
constexpr int CR  = 48;
constexpr int CPW = CR + 2*CN;      // 176
constexpr int CBT   = CB*CT;        // 8192
constexpr int CBTDM = CBT*CDM;
constexpr int CBTDI = CBT*CDI;

constexpr int NIW = 2*2*CDI*CDM;
constexpr int NXW = 2*CPW*CDI;
constexpr int NDW = 2*CDI*CR;
constexpr int NOW = 2*CDM*CDI;

#define LOG2E_F 1.4426950408889634f

// ---------------- fp32 scratch ----------------
__device__ float g_x   [CBTDM];
__device__ float g_proj[CBT*CPW];
__device__ float g_ho  [CBTDM];

// ---------------- fp16 planes ----------------
__device__ __half g_xza[CBT*2*CDI];
__device__ __half g_xa [CBTDM];
__device__ __half g_uca[CBTDI];
__device__ __half g_del[CBTDI];
__device__ __half g_dta[CBT*CR];
__device__ __half g_ya [CBTDI];
__device__ __half g_iw[NIW];
__device__ __half g_xw[NXW];
__device__ __half g_dw[NDW];
__device__ __half g_ow[NOW];

// ---------------- helpers ----------------
__device__ __forceinline__ float ex2f(float x){
    float r; asm("ex2.approx.ftz.f32 %0, %1;" : "=f"(r) : "f"(x)); return r;
}
__device__ __forceinline__ float softplusf(float x){
    if (x > 20.f) return x;
    return log1pf(__expf(x));
}
__device__ __forceinline__ void ldsm4(uint32_t r[4], uint32_t saddr){
    asm volatile("ldmatrix.sync.aligned.m8n8.x4.shared.b16 {%0,%1,%2,%3}, [%4];"
        : "=r"(r[0]),"=r"(r[1]),"=r"(r[2]),"=r"(r[3]) : "r"(saddr));
}
__device__ __forceinline__ void mma16816(float c[4], const uint32_t a[4], uint32_t b0, uint32_t b1){
    asm volatile("mma.sync.aligned.m16n8k16.row.col.f32.f16.f16.f32 "
        "{%0,%1,%2,%3}, {%4,%5,%6,%7}, {%8,%9}, {%0,%1,%2,%3};"
        : "+f"(c[0]),"+f"(c[1]),"+f"(c[2]),"+f"(c[3])
        : "r"(a[0]),"r"(a[1]),"r"(a[2]),"r"(a[3]), "r"(b0),"r"(b1));
}
__device__ __forceinline__ void cpa16(uint32_t dst, const void* src, int sz){
    asm volatile("cp.async.cg.shared.global [%0], [%1], 16, %2;"
        :: "r"(dst), "l"(src), "r"(sz));
}
#define CP_COMMIT() asm volatile("cp.async.commit_group;")
#define CP_WAIT1()  asm volatile("cp.async.wait_group 1;")

// ---------------- mask + fp16 round ----------------
__global__ void mask_kernel(const float* __restrict__ x, const float* __restrict__ m){
    int idx = blockIdx.x*256 + threadIdx.x;
    if (idx >= CBTDM) return;
    float v = x[idx] * m[idx / CDM];
    g_x[idx]  = v;
    g_xa[idx] = __float2half_rn(v);
}

// ---------------- fused weight convert ----------------
__global__ void wconv_all(const float* __restrict__ iw, const float* __restrict__ xw,
                          const float* __restrict__ dtw, const float* __restrict__ ow){
    int idx = blockIdx.x*256 + threadIdx.x;
    if (idx < NIW){ g_iw[idx] = __float2half_rn(iw[idx]); return; }
    idx -= NIW;
    if (idx < NXW){ g_xw[idx] = __float2half_rn(xw[idx]); return; }
    idx -= NXW;
    if (idx < NDW){ g_dw[idx] = __float2half_rn(dtw[idx]); return; }
    idx -= NDW;
    if (idx < NOW){ g_ow[idx] = __float2half_rn(ow[idx]); }
}

// ---------------- pipelined fp16 tensor-core GEMM (single pass, BK=32) ----------------
// BM x 128 tile (BM=128 or 64), 256 threads, 3-stage cp.async ring, 2 CTAs/SM.
// BM=128: 8 warps as 4x2 (32m x 64n each).  BM=64: 8 warps as 2x4 (32m x 32n each).
// EPI: 0 plain, 1 softplus(acc+bias[n]), 2 plain + dt fp16 plane (cols<CR)
template<int EPI, typename OutT, int BM>
__global__ void __launch_bounds__(256, 2) gemm_f16(
    const __half* __restrict__ A, int lda,
    const __half* __restrict__ B, int ldb,
    OutT* __restrict__ C, int ldc,
    int M, int N, int K, const float* __restrict__ bias)
{
    constexpr int LDS = 40;
    constexpr int PLANE_A = BM*LDS;
    constexpr int PLANE_B = 128*LDS;
    constexpr int STAGE = PLANE_A + PLANE_B;
    constexpr int NF = (BM == 128) ? 8 : 4;      // n-frags of 8 per warp
    constexpr int NV = (BM + 128) / 64;          // cpa16 ops per thread per slab
    extern __shared__ __align__(16) uint16_t smem[];

    const int tid  = threadIdx.x;
    const int bm   = blockIdx.y * BM;
    const int bn   = blockIdx.x << 7;
    const int lane = tid & 31;
    const int warp = tid >> 5;
    const int wm   = (BM == 128) ? ((warp >> 1) << 5) : ((warp >> 2) << 5);
    const int wn   = (BM == 128) ? ((warp & 1) << 6)  : ((warp & 3) << 5);

    float c[2][NF][4];
    #pragma unroll
    for (int i=0;i<2;i++) for (int j=0;j<NF;j++) for (int k=0;k<4;k++) c[i][j][k]=0.f;

    const int nk = (K + 31) >> 5;

    auto issue_copy = [&](int it){
        int s  = it % 3;
        int k0 = it << 5;
        #pragma unroll
        for (int i=0;i<NV;i++){
            int idx = i*256 + tid;
            uint16_t* dst;
            const __half* base; int ld, grow; bool okr;
            int row, ch;
            if (idx < BM*4){
                row = idx >> 2; ch = idx & 3;
                dst = smem + s*STAGE + row*LDS + ch*8;
                base = A; ld = lda; grow = bm + row; okr = true;
            } else {
                int j = idx - BM*4;
                row = j >> 2; ch = j & 3;
                dst = smem + s*STAGE + PLANE_A + row*LDS + ch*8;
                base = B; ld = ldb; grow = bn + row; okr = (grow < N);
            }
            int kk = k0 + ch*8;
            bool ok = okr && (kk < K);
            uint32_t d = (uint32_t)__cvta_generic_to_shared(dst);
            const __half* src = ok ? (base + (size_t)grow*ld + kk) : base;
            cpa16(d, src, ok ? 16 : 0);
        }
        CP_COMMIT();
    };

    issue_copy(0);
    if (nk > 1) issue_copy(1); else CP_COMMIT();

    for (int it = 0; it < nk; it++){
        CP_WAIT1();
        __syncthreads();

        const int s = it % 3;
        const uint16_t* pA = smem + s*STAGE;
        const uint16_t* pB = pA + PLANE_A;

        #pragma unroll
        for (int ks = 0; ks < 2; ks++){
            uint32_t af[2][4];
            int arow = (lane & 7) + ((lane >> 3) & 1) * 8;
            int akc  = ks*16 + ((lane & 16) ? 8 : 0);
            #pragma unroll
            for (int mf=0; mf<2; mf++)
                ldsm4(af[mf], (uint32_t)__cvta_generic_to_shared(
                    &pA[(wm + mf*16 + arow)*LDS + akc]));

            int bgrp = lane >> 3;
            int brow = (lane & 7) + ((bgrp >= 2) ? 8 : 0);
            int bkc  = ks*16 + ((bgrp & 1) ? 8 : 0);

            uint32_t bfr[NF][2];
            #pragma unroll
            for (int p=0; p<NF/2; p++){
                uint32_t r4[4];
                ldsm4(r4, (uint32_t)__cvta_generic_to_shared(
                    &pB[(wn + p*16 + brow)*LDS + bkc]));
                bfr[2*p  ][0]=r4[0]; bfr[2*p  ][1]=r4[1];
                bfr[2*p+1][0]=r4[2]; bfr[2*p+1][1]=r4[3];
            }
            #pragma unroll
            for (int mf=0; mf<2; mf++)
                #pragma unroll
                for (int nf=0; nf<NF; nf++)
                    mma16816(c[mf][nf], af[mf], bfr[nf][0], bfr[nf][1]);
        }

        if (it + 2 < nk) issue_copy(it + 2);
        else             CP_COMMIT();
    }

    // ---- epilogue ----
    #pragma unroll
    for (int mf=0; mf<2; mf++){
        int r0 = bm + wm + mf*16 + (lane >> 2);
        #pragma unroll
        for (int nf=0; nf<NF; nf++){
            int cc = bn + wn + nf*8 + (lane & 3)*2;
            float v0 = c[mf][nf][0], v1 = c[mf][nf][1];
            float v2 = c[mf][nf][2], v3 = c[mf][nf][3];
            if (EPI == 1){
                if (cc   < N){ v0 = softplusf(v0 + bias[cc]);   v2 = softplusf(v2 + bias[cc]); }
                if (cc+1 < N){ v1 = softplusf(v1 + bias[cc+1]); v3 = softplusf(v3 + bias[cc+1]); }
            }
            if (cc + 1 < N){
                if constexpr (sizeof(OutT) == 2){
                    *(__half2*)&C[(size_t)r0*ldc + cc] =
                        __halves2half2(__float2half_rn(v0), __float2half_rn(v1));
                    *(__half2*)&C[(size_t)(r0+8)*ldc + cc] =
                        __halves2half2(__float2half_rn(v2), __float2half_rn(v3));
                } else {
                    *(float2*)&C[(size_t)r0*ldc + cc]     = make_float2(v0, v1);
                    *(float2*)&C[(size_t)(r0+8)*ldc + cc] = make_float2(v2, v3);
                }
            } else if (cc < N){
                C[(size_t)r0*ldc + cc]     = (OutT)v0;
                C[(size_t)(r0+8)*ldc + cc] = (OutT)v2;
            }
            if (EPI == 2){
                if (cc < CR){
                    g_dta[(size_t)r0*CR + cc]     = __float2half_rn(v0);
                    g_dta[(size_t)(r0+8)*CR + cc] = __float2half_rn(v2);
                }
                if (cc + 1 < CR){
                    g_dta[(size_t)r0*CR + cc+1]     = __float2half_rn(v1);
                    g_dta[(size_t)(r0+8)*CR + cc+1] = __float2half_rn(v3);
                }
            }
        }
    }
}

// ---------------- depthwise conv (DC=4) + SiLU, sliding window: 4 t's/thread ----------------
__global__ void conv_silu_kernel(const float* __restrict__ cw, const float* __restrict__ cb){
    int idx = blockIdx.x*256 + threadIdx.x;
    if (idx >= (CBT/4)*(CDI/2)) return;
    int d2  = idx % (CDI/2);
    int rem = idx / (CDI/2);
    int b   = rem / (CT/4);
    int t4  = (rem % (CT/4)) * 4;
    int d   = d2*2;

    const __half2* rows = reinterpret_cast<const __half2*>(g_xza + (size_t)b*CT*(2*CDI));
    float2 vv[7];
    #pragma unroll
    for (int j=0;j<7;j++){
        int t = t4 - 3 + j;
        vv[j] = (t >= 0) ? __half22float2(rows[(size_t)t*CDI + d2])
                         : make_float2(0.f, 0.f);
    }
    float w0a = cw[d*4+0], w1a = cw[d*4+1], w2a = cw[d*4+2], w3a = cw[d*4+3];
    float w0b = cw[(d+1)*4+0], w1b = cw[(d+1)*4+1], w2b = cw[(d+1)*4+2], w3b = cw[(d+1)*4+3];
    float cba = cb[d], cbb = cb[d+1];

    __half2* outp = reinterpret_cast<__half2*>(g_uca) + (size_t)(b*CT + t4)*(CDI/2) + d2;
    #pragma unroll
    for (int k=0;k<4;k++){
        float a0 = cba + w0a*vv[k].x + w1a*vv[k+1].x + w2a*vv[k+2].x + w3a*vv[k+3].x;
        float a1 = cbb + w0b*vv[k].y + w1b*vv[k+1].y + w2b*vv[k+2].y + w3b*vv[k+3].y;
        float s0 = a0 / (1.f + __expf(-a0));
        float s1 = a1 / (1.f + __expf(-a1));
        outp[(size_t)k*(CDI/2)] = __halves2half2(__float2half_rn(s0), __float2half_rn(s1));
    }
}

// ---------------- selective scan (R13 structure) ----------------
__global__ void __launch_bounds__(128) scan_kernel(
    const float* __restrict__ alog,
    const float* __restrict__ Dp)
{
    __shared__ float sB[64][64];
    __shared__ float sC[64][64];
    __shared__ float sdel[64][16];
    __shared__ float su  [64][16];
    __shared__ float sz  [64][16];

    const int b     = blockIdx.y;
    const int dbase = blockIdx.x * 16;
    const int tid   = threadIdx.x;
    const int lane  = tid & 31;
    const int warp  = tid >> 5;
    const int g = lane >> 3, q = lane & 7;
    const int dl = warp*4 + g;
    const int d  = dbase + dl;

    float h[8], aa[8];
    #pragma unroll
    for (int j=0;j<8;j++){
        h[j]  = 0.f;
        aa[j] = -__expf(alog[d*CN + q*8 + j]) * LOG2E_F;
    }
    const float Dd = Dp[d];

    const float step = (aa[7] - aa[0]) * (1.f/7.f);
    float amax = fmaxf(fabsf(aa[0]), fabsf(aa[7]));
    bool geo = true;
    #pragma unroll
    for (int j=0;j<8;j++)
        geo = geo && (fabsf(aa[j] - (aa[0] + j*step)) <= 1e-4f*amax + 1e-7f);
    geo = __all_sync(0xffffffffu, geo);
    const float aa0 = aa[0];

    for (int t0 = 0; t0 < CT; t0 += 64){
        const size_t rowbase = (size_t)b*CT + t0;
        for (int i = tid; i < 64*128; i += 128){
            int tt = i >> 7, c = i & 127;
            float v = g_proj[(rowbase+tt)*CPW + CR + c];
            if (c < 64) sB[tt][c] = v; else sC[tt][c-64] = v;
        }
        for (int i = tid; i < 64*16; i += 128){
            int tt = i >> 4, dd = i & 15;
            size_t r = rowbase + tt;
            sdel[tt][dd] = __half2float(g_del[r*CDI + dbase + dd]);
            su[tt][dd]   = __half2float(g_uca[r*CDI + dbase + dd]);
            sz[tt][dd]   = __half2float(g_xza[r*(2*CDI) + CDI + dbase + dd]);
        }
        __syncthreads();

        if (geo){
            #pragma unroll 2
            for (int tt=0; tt<64; tt++){
                float dlt = sdel[tt][dl];
                float u   = su[tt][dl];
                float du  = dlt * u;
                float4 B0 = *(const float4*)&sB[tt][q*8];
                float4 B1 = *(const float4*)&sB[tt][q*8+4];
                float4 C0 = *(const float4*)&sC[tt][q*8];
                float4 C1 = *(const float4*)&sC[tt][q*8+4];
                float Bv[8] = {B0.x,B0.y,B0.z,B0.w,B1.x,B1.y,B1.z,B1.w};
                float Cv[8] = {C0.x,C0.y,C0.z,C0.w,C1.x,C1.y,C1.z,C1.w};
                float e0 = ex2f(dlt*aa0);
                float rr = ex2f(dlt*step);
                float rr2 = rr*rr, rr4 = rr2*rr2;
                float ev[8];
                ev[0]=e0;        ev[1]=e0*rr;
                ev[2]=ev[0]*rr2; ev[3]=ev[1]*rr2;
                ev[4]=ev[0]*rr4; ev[5]=ev[1]*rr4;
                ev[6]=ev[2]*rr4; ev[7]=ev[3]*rr4;
                float yp = 0.f;
                #pragma unroll
                for (int j=0;j<8;j++){
                    h[j] = h[j]*ev[j] + du*Bv[j];
                    yp += h[j]*Cv[j];
                }
                yp += __shfl_xor_sync(0xffffffffu, yp, 1);
                yp += __shfl_xor_sync(0xffffffffu, yp, 2);
                yp += __shfl_xor_sync(0xffffffffu, yp, 4);
                if (q == 0){
                    float z = sz[tt][dl];
                    float s = 1.f/(1.f + __expf(-z));
                    float v = (yp + u*Dd) * (z*s);
                    g_ya[(rowbase+tt)*CDI + d] = __float2half_rn(v);
                }
            }
        } else {
            #pragma unroll 2
            for (int tt=0; tt<64; tt++){
                float dlt = sdel[tt][dl];
                float u   = su[tt][dl];
                float du  = dlt * u;
                float4 B0 = *(const float4*)&sB[tt][q*8];
                float4 B1 = *(const float4*)&sB[tt][q*8+4];
                float4 C0 = *(const float4*)&sC[tt][q*8];
                float4 C1 = *(const float4*)&sC[tt][q*8+4];
                float Bv[8] = {B0.x,B0.y,B0.z,B0.w,B1.x,B1.y,B1.z,B1.w};
                float Cv[8] = {C0.x,C0.y,C0.z,C0.w,C1.x,C1.y,C1.z,C1.w};
                float yp = 0.f;
                #pragma unroll
                for (int j=0;j<8;j++){
                    h[j] = h[j]*ex2f(dlt*aa[j]) + du*Bv[j];
                    yp += h[j]*Cv[j];
                }
                yp += __shfl_xor_sync(0xffffffffu, yp, 1);
                yp += __shfl_xor_sync(0xffffffffu, yp, 2);
                yp += __shfl_xor_sync(0xffffffffu, yp, 4);
                if (q == 0){
                    float z = sz[tt][dl];
                    float s = 1.f/(1.f + __expf(-z));
                    float v = (yp + u*Dd) * (z*s);
                    g_ya[(rowbase+tt)*CDI + d] = __float2half_rn(v);
                }
            }
        }
        __syncthreads();
    }
}

// ---------------- LayerNorm + FiLM + residual ----------------
__device__ __forceinline__ float blockReduceSum(float v){
    __shared__ float sh[8];
    __shared__ float tot;
    int lane = threadIdx.x & 31, w = threadIdx.x >> 5;
    #pragma unroll
    for (int o=16;o;o>>=1) v += __shfl_down_sync(0xffffffffu, v, o);
    if (!lane) sh[w] = v;
    __syncthreads();
    v = (threadIdx.x < 8) ? sh[threadIdx.x] : 0.f;
    if (w == 0){
        #pragma unroll
        for (int o=4;o;o>>=1) v += __shfl_down_sync(0xffffffffu, v, o);
    }
    if (threadIdx.x == 0) tot = v;
    __syncthreads();
    return tot;
}

template<int SPLIT>
__global__ void __launch_bounds__(256) ln_film_res_kernel(
    const float* __restrict__ gamma, const float* __restrict__ beta,
    const float* __restrict__ w, const float* __restrict__ bln,
    float* __restrict__ out)
{
    const int row = blockIdx.x;
    const int tid = threadIdx.x;
    const size_t base = (size_t)row*CDM;
    float v0 = g_ho[base+tid], v1 = g_ho[base+tid+256], v2 = g_ho[base+tid+512];
    float mean = blockReduceSum(v0+v1+v2) * (1.f/CDM);
    float d0 = v0-mean, d1 = v1-mean, d2 = v2-mean;
    float var = blockReduceSum(d0*d0 + d1*d1 + d2*d2) * (1.f/CDM);
    float rstd = rsqrtf(var + 1e-5f);
    float dv[3] = {d0, d1, d2};
    #pragma unroll
    for (int k=0;k<3;k++){
        int c = tid + k*256;
        float o = dv[k]*rstd*w[c] + bln[c];
        float v = gamma[base+c]*o + beta[base+c] + g_x[base+c];
        out[base+c] = v;
        if (SPLIT) g_xa[base+c] = __float2half_rn(v);
    }
}

// ---------------- launch ----------------
extern "C" void kernel_launch(void* const* d_in, const int* in_sizes, int n_in,
                              void* d_out, int out_size)
{
    (void)in_sizes; (void)n_in; (void)out_size;
    const float* x     = (const float*)d_in[0];
    const float* mask  = (const float*)d_in[1];
    const float* fgam  = (const float*)d_in[2];
    const float* fbet  = (const float*)d_in[3];
    const float* in_w  = (const float*)d_in[4];
    const float* cw    = (const float*)d_in[5];
    const float* cb    = (const float*)d_in[6];
    const float* xw    = (const float*)d_in[7];
    const float* dtw   = (const float*)d_in[8];
    const float* dtb   = (const float*)d_in[9];
    const float* alog  = (const float*)d_in[10];
    const float* Dp    = (const float*)d_in[11];
    const float* ow    = (const float*)d_in[12];
    const float* lnw   = (const float*)d_in[13];
    const float* lnb   = (const float*)d_in[14];

    float *gx, *gproj, *gho;
    cudaGetSymbolAddress((void**)&gx,   g_x);
    cudaGetSymbolAddress((void**)&gproj,g_proj);
    cudaGetSymbolAddress((void**)&gho,  g_ho);

    __half *xza, *xa, *uca, *dela, *dta, *ya, *iw, *xwp, *dw, *owp;
    cudaGetSymbolAddress((void**)&xza,  g_xza);
    cudaGetSymbolAddress((void**)&xa,   g_xa);
    cudaGetSymbolAddress((void**)&uca,  g_uca);
    cudaGetSymbolAddress((void**)&dela, g_del);
    cudaGetSymbolAddress((void**)&dta,  g_dta);
    cudaGetSymbolAddress((void**)&ya,   g_ya);
    cudaGetSymbolAddress((void**)&iw,   g_iw);
    cudaGetSymbolAddress((void**)&xwp,  g_xw);
    cudaGetSymbolAddress((void**)&dw,   g_dw);
    cudaGetSymbolAddress((void**)&owp,  g_ow);

    const int SMEM128 = 3*(128+128)*40*2;   // 61440 B
    const int SMEM64  = 3*(64+128)*40*2;    // 46080 B
    cudaFuncSetAttribute(gemm_f16<0,__half,128>, cudaFuncAttributeMaxDynamicSharedMemorySize, SMEM128);
    cudaFuncSetAttribute(gemm_f16<1,__half,128>, cudaFuncAttributeMaxDynamicSharedMemorySize, SMEM128);
    cudaFuncSetAttribute(gemm_f16<2,float,64>,   cudaFuncAttributeMaxDynamicSharedMemorySize, SMEM64);
    cudaFuncSetAttribute(gemm_f16<0,float,64>,   cudaFuncAttributeMaxDynamicSharedMemorySize, SMEM64);

    mask_kernel<<<(CBTDM + 255)/256, 256>>>(x, mask);
    {
        int n = NIW + NXW + NDW + NOW;
        wconv_all<<<(n+255)/256, 256>>>(in_w, xw, dtw, ow);
    }

    for (int l = 0; l < 2; l++){
        // xz = x @ W_in^T -> fp16  [8192 x 3072 x 768]  (BM=128, 1536 CTAs)
        gemm_f16<0,__half,128><<<dim3(24,64), 256, SMEM128>>>(
            xa, CDM, iw + (size_t)l*NIW/2, CDM,
            xza, 2*CDI, CBT, 2*CDI, CDM, nullptr);
        // depthwise conv + silu (sliding window, 4 t/thread)
        conv_silu_kernel<<<((CBT/4)*(CDI/2) + 255)/256, 256>>>(cw + (size_t)l*CDI*4, cb + (size_t)l*CDI);
        // proj = u_c @ W_x^T -> fp32 (+ dt plane)  [8192 x 176 x 1536]  (BM=64, 256 CTAs)
        gemm_f16<2,float,64><<<dim3(2,128), 256, SMEM64>>>(
            uca, CDI, xwp + (size_t)l*NXW/2, CDI,
            gproj, CPW, CBT, CPW, CDI, nullptr);
        // delta = softplus(dt @ W_dt^T + b) -> fp16  [8192 x 1536 x 48]  (BM=128)
        gemm_f16<1,__half,128><<<dim3(12,64), 256, SMEM128>>>(
            dta, CR, dw + (size_t)l*NDW/2, CR,
            dela, CDI, CBT, CDI, CR, dtb + (size_t)l*CDI);
        // selective scan -> fp16 y
        scan_kernel<<<dim3(CDI/16, CB), 128>>>(alog + (size_t)l*CDI*CN, Dp + (size_t)l*CDI);
        // h_out = y @ W_out^T -> fp32  [8192 x 768 x 1536]  (BM=64, 768 CTAs)
        gemm_f16<0,float,64><<<dim3(6,128), 256, SMEM64>>>(
            ya, CDI, owp + (size_t)l*NOW/2, CDI,
            gho, CDM, CBT, CDM, CDI, nullptr);
        // LN + FiLM + residual
        if (l == 0)
            ln_film_res_kernel<1><<<CBT, 256>>>(fgam, fbet, lnw, lnb, gx);
        else
            ln_film_res_kernel<0><<<CBT, 256>>>(fgam + (size_t)CBTDM, fbet + (size_t)CBTDM,
                                                lnw + CDM, lnb + CDM, (float*)d_out);
    }
}

// round 15
// speedup vs baseline: 1.5774x; 1.0046x over previous
#include <cuda_runtime.h>
#include <cuda_fp16.h>
#include <math.h>
#include <stdint.h>

// ---------------- problem constants ----------------
constexpr int CB  = 4;
constexpr int CT  = 2048;
constexpr int CDM = 768;
constexpr int CDI = 1536;
constexpr int CN  = 64;
constexpr int CR  = 48;
constexpr int CPW = CR + 2*CN;      // 176
constexpr int CBT   = CB*CT;        // 8192
constexpr int CBTDM = CBT*CDM;
constexpr int CBTDI = CBT*CDI;

constexpr int NIW = 2*2*CDI*CDM;
constexpr int NXW = 2*CPW*CDI;
constexpr int NDW = 2*CDI*CR;
constexpr int NOW = 2*CDM*CDI;

#define LOG2E_F 1.4426950408889634f

// ---------------- fp32 scratch ----------------
__device__ float g_x   [CBTDM];
__device__ float g_proj[CBT*CPW];
__device__ float g_ho  [CBTDM];

// ---------------- fp16 planes ----------------
__device__ __half g_xza[CBT*2*CDI];
__device__ __half g_xa [CBTDM];
__device__ __half g_uca[CBTDI];
__device__ __half g_del[CBTDI];
__device__ __half g_dta[CBT*CR];
__device__ __half g_ya [CBTDI];
__device__ __half g_iw[NIW];
__device__ __half g_xw[NXW];
__device__ __half g_dw[NDW];
__device__ __half g_ow[NOW];

// ---------------- helpers ----------------
__device__ __forceinline__ float ex2f(float x){
    float r; asm("ex2.approx.ftz.f32 %0, %1;" : "=f"(r) : "f"(x)); return r;
}
__device__ __forceinline__ float softplusf(float x){
    if (x > 20.f) return x;
    return log1pf(__expf(x));
}
__device__ __forceinline__ void ldsm4(uint32_t r[4], uint32_t saddr){
    asm volatile("ldmatrix.sync.aligned.m8n8.x4.shared.b16 {%0,%1,%2,%3}, [%4];"
        : "=r"(r[0]),"=r"(r[1]),"=r"(r[2]),"=r"(r[3]) : "r"(saddr));
}
__device__ __forceinline__ void mma16816(float c[4], const uint32_t a[4], uint32_t b0, uint32_t b1){
    asm volatile("mma.sync.aligned.m16n8k16.row.col.f32.f16.f16.f32 "
        "{%0,%1,%2,%3}, {%4,%5,%6,%7}, {%8,%9}, {%0,%1,%2,%3};"
        : "+f"(c[0]),"+f"(c[1]),"+f"(c[2]),"+f"(c[3])
        : "r"(a[0]),"r"(a[1]),"r"(a[2]),"r"(a[3]), "r"(b0),"r"(b1));
}
__device__ __forceinline__ void cpa16(uint32_t dst, const void* src, int sz){
    asm volatile("cp.async.cg.shared.global [%0], [%1], 16, %2;"
        :: "r"(dst), "l"(src), "r"(sz));
}
#define CP_COMMIT() asm volatile("cp.async.commit_group;")
#define CP_WAIT1()  asm volatile("cp.async.wait_group 1;")

// ---------------- mask + fp16 round ----------------
__global__ void mask_kernel(const float* __restrict__ x, const float* __restrict__ m){
    int idx = blockIdx.x*256 + threadIdx.x;
    if (idx >= CBTDM) return;
    float v = x[idx] * m[idx / CDM];
    g_x[idx]  = v;
    g_xa[idx] = __float2half_rn(v);
}

// ---------------- fused weight convert ----------------
__global__ void wconv_all(const float* __restrict__ iw, const float* __restrict__ xw,
                          const float* __restrict__ dtw, const float* __restrict__ ow){
    int idx = blockIdx.x*256 + threadIdx.x;
    if (idx < NIW){ g_iw[idx] = __float2half_rn(iw[idx]); return; }
    idx -= NIW;
    if (idx < NXW){ g_xw[idx] = __float2half_rn(xw[idx]); return; }
    idx -= NXW;
    if (idx < NDW){ g_dw[idx] = __float2half_rn(dtw[idx]); return; }
    idx -= NDW;
    if (idx < NOW){ g_ow[idx] = __float2half_rn(ow[idx]); }
}

// ---------------- pipelined fp16 tensor-core GEMM (single pass, BK=32) ----------------
// BM x 128 tile (BM=128 or 64), 256 threads, 3-stage cp.async ring, 2 CTAs/SM.
template<int EPI, typename OutT, int BM>
__global__ void __launch_bounds__(256, 2) gemm_f16(
    const __half* __restrict__ A, int lda,
    const __half* __restrict__ B, int ldb,
    OutT* __restrict__ C, int ldc,
    int M, int N, int K, const float* __restrict__ bias)
{
    constexpr int LDS = 40;
    constexpr int PLANE_A = BM*LDS;
    constexpr int PLANE_B = 128*LDS;
    constexpr int STAGE = PLANE_A + PLANE_B;
    constexpr int NF = (BM == 128) ? 8 : 4;
    constexpr int NV = (BM + 128) / 64;
    extern __shared__ __align__(16) uint16_t smem[];

    const int tid  = threadIdx.x;
    const int bm   = blockIdx.y * BM;
    const int bn   = blockIdx.x << 7;
    const int lane = tid & 31;
    const int warp = tid >> 5;
    const int wm   = (BM == 128) ? ((warp >> 1) << 5) : ((warp >> 2) << 5);
    const int wn   = (BM == 128) ? ((warp & 1) << 6)  : ((warp & 3) << 5);

    float c[2][NF][4];
    #pragma unroll
    for (int i=0;i<2;i++) for (int j=0;j<NF;j++) for (int k=0;k<4;k++) c[i][j][k]=0.f;

    const int nk = (K + 31) >> 5;

    auto issue_copy = [&](int it){
        int s  = it % 3;
        int k0 = it << 5;
        #pragma unroll
        for (int i=0;i<NV;i++){
            int idx = i*256 + tid;
            uint16_t* dst;
            const __half* base; int ld, grow; bool okr;
            int row, ch;
            if (idx < BM*4){
                row = idx >> 2; ch = idx & 3;
                dst = smem + s*STAGE + row*LDS + ch*8;
                base = A; ld = lda; grow = bm + row; okr = true;
            } else {
                int j = idx - BM*4;
                row = j >> 2; ch = j & 3;
                dst = smem + s*STAGE + PLANE_A + row*LDS + ch*8;
                base = B; ld = ldb; grow = bn + row; okr = (grow < N);
            }
            int kk = k0 + ch*8;
            bool ok = okr && (kk < K);
            uint32_t d = (uint32_t)__cvta_generic_to_shared(dst);
            const __half* src = ok ? (base + (size_t)grow*ld + kk) : base;
            cpa16(d, src, ok ? 16 : 0);
        }
        CP_COMMIT();
    };

    issue_copy(0);
    if (nk > 1) issue_copy(1); else CP_COMMIT();

    for (int it = 0; it < nk; it++){
        CP_WAIT1();
        __syncthreads();

        const int s = it % 3;
        const uint16_t* pA = smem + s*STAGE;
        const uint16_t* pB = pA + PLANE_A;

        #pragma unroll
        for (int ks = 0; ks < 2; ks++){
            uint32_t af[2][4];
            int arow = (lane & 7) + ((lane >> 3) & 1) * 8;
            int akc  = ks*16 + ((lane & 16) ? 8 : 0);
            #pragma unroll
            for (int mf=0; mf<2; mf++)
                ldsm4(af[mf], (uint32_t)__cvta_generic_to_shared(
                    &pA[(wm + mf*16 + arow)*LDS + akc]));

            int bgrp = lane >> 3;
            int brow = (lane & 7) + ((bgrp >= 2) ? 8 : 0);
            int bkc  = ks*16 + ((bgrp & 1) ? 8 : 0);

            uint32_t bfr[NF][2];
            #pragma unroll
            for (int p=0; p<NF/2; p++){
                uint32_t r4[4];
                ldsm4(r4, (uint32_t)__cvta_generic_to_shared(
                    &pB[(wn + p*16 + brow)*LDS + bkc]));
                bfr[2*p  ][0]=r4[0]; bfr[2*p  ][1]=r4[1];
                bfr[2*p+1][0]=r4[2]; bfr[2*p+1][1]=r4[3];
            }
            #pragma unroll
            for (int mf=0; mf<2; mf++)
                #pragma unroll
                for (int nf=0; nf<NF; nf++)
                    mma16816(c[mf][nf], af[mf], bfr[nf][0], bfr[nf][1]);
        }

        if (it + 2 < nk) issue_copy(it + 2);
        else             CP_COMMIT();
    }

    // ---- epilogue ----
    #pragma unroll
    for (int mf=0; mf<2; mf++){
        int r0 = bm + wm + mf*16 + (lane >> 2);
        #pragma unroll
        for (int nf=0; nf<NF; nf++){
            int cc = bn + wn + nf*8 + (lane & 3)*2;
            float v0 = c[mf][nf][0], v1 = c[mf][nf][1];
            float v2 = c[mf][nf][2], v3 = c[mf][nf][3];
            if (EPI == 1){
                if (cc   < N){ v0 = softplusf(v0 + bias[cc]);   v2 = softplusf(v2 + bias[cc]); }
                if (cc+1 < N){ v1 = softplusf(v1 + bias[cc+1]); v3 = softplusf(v3 + bias[cc+1]); }
            }
            if (cc + 1 < N){
                if constexpr (sizeof(OutT) == 2){
                    *(__half2*)&C[(size_t)r0*ldc + cc] =
                        __halves2half2(__float2half_rn(v0), __float2half_rn(v1));
                    *(__half2*)&C[(size_t)(r0+8)*ldc + cc] =
                        __halves2half2(__float2half_rn(v2), __float2half_rn(v3));
                } else {
                    *(float2*)&C[(size_t)r0*ldc + cc]     = make_float2(v0, v1);
                    *(float2*)&C[(size_t)(r0+8)*ldc + cc] = make_float2(v2, v3);
                }
            } else if (cc < N){
                C[(size_t)r0*ldc + cc]     = (OutT)v0;
                C[(size_t)(r0+8)*ldc + cc] = (OutT)v2;
            }
            if (EPI == 2){
                if (cc < CR){
                    g_dta[(size_t)r0*CR + cc]     = __float2half_rn(v0);
                    g_dta[(size_t)(r0+8)*CR + cc] = __float2half_rn(v2);
                }
                if (cc + 1 < CR){
                    g_dta[(size_t)r0*CR + cc+1]     = __float2half_rn(v1);
                    g_dta[(size_t)(r0+8)*CR + cc+1] = __float2half_rn(v3);
                }
            }
        }
    }
}

// ---------------- depthwise conv (DC=4) + SiLU, sliding window: 4 t's/thread ----------------
__global__ void conv_silu_kernel(const float* __restrict__ cw, const float* __restrict__ cb){
    int idx = blockIdx.x*256 + threadIdx.x;
    if (idx >= (CBT/4)*(CDI/2)) return;
    int d2  = idx % (CDI/2);
    int rem = idx / (CDI/2);
    int b   = rem / (CT/4);
    int t4  = (rem % (CT/4)) * 4;
    int d   = d2*2;

    const __half2* rows = reinterpret_cast<const __half2*>(g_xza + (size_t)b*CT*(2*CDI));
    float2 vv[7];
    #pragma unroll
    for (int j=0;j<7;j++){
        int t = t4 - 3 + j;
        vv[j] = (t >= 0) ? __half22float2(rows[(size_t)t*CDI + d2])
                         : make_float2(0.f, 0.f);
    }
    float w0a = cw[d*4+0], w1a = cw[d*4+1], w2a = cw[d*4+2], w3a = cw[d*4+3];
    float w0b = cw[(d+1)*4+0], w1b = cw[(d+1)*4+1], w2b = cw[(d+1)*4+2], w3b = cw[(d+1)*4+3];
    float cba = cb[d], cbb = cb[d+1];

    __half2* outp = reinterpret_cast<__half2*>(g_uca) + (size_t)(b*CT + t4)*(CDI/2) + d2;
    #pragma unroll
    for (int k=0;k<4;k++){
        float a0 = cba + w0a*vv[k].x + w1a*vv[k+1].x + w2a*vv[k+2].x + w3a*vv[k+3].x;
        float a1 = cbb + w0b*vv[k].y + w1b*vv[k+1].y + w2b*vv[k+2].y + w3b*vv[k+3].y;
        float s0 = a0 / (1.f + __expf(-a0));
        float s1 = a1 / (1.f + __expf(-a1));
        outp[(size_t)k*(CDI/2)] = __halves2half2(__float2half_rn(s0), __float2half_rn(s1));
    }
}

// ---------------- selective scan: 16 lanes/channel x 4 states, 256 threads ----------------
// Block covers one b and 16 d's.  Warp = 2 d's (g = lane>>4), lane owns states q*4..q*4+3.
__global__ void __launch_bounds__(256) scan_kernel(
    const float* __restrict__ alog,
    const float* __restrict__ Dp)
{
    __shared__ float sB[64][64];
    __shared__ float sC[64][64];
    __shared__ float sdel[64][16];
    __shared__ float su  [64][16];
    __shared__ float sz  [64][16];

    const int b     = blockIdx.y;
    const int dbase = blockIdx.x * 16;
    const int tid   = threadIdx.x;
    const int lane  = tid & 31;
    const int warp  = tid >> 5;
    const int g = lane >> 4;          // 0..1 channel within warp
    const int q = lane & 15;          // 0..15 lane within channel
    const int dl = warp*2 + g;        // 0..15
    const int d  = dbase + dl;

    float h[4], aa[4];
    #pragma unroll
    for (int j=0;j<4;j++){
        h[j]  = 0.f;
        aa[j] = -__expf(alog[d*CN + q*4 + j]) * LOG2E_F;
    }
    const float Dd = Dp[d];

    // arithmetic-progression detection across the lane's 4 states (warp-uniform)
    const float step = (aa[3] - aa[0]) * (1.f/3.f);
    float amax = fmaxf(fabsf(aa[0]), fabsf(aa[3]));
    bool geo = true;
    #pragma unroll
    for (int j=0;j<4;j++)
        geo = geo && (fabsf(aa[j] - (aa[0] + j*step)) <= 1e-4f*amax + 1e-7f);
    geo = __all_sync(0xffffffffu, geo);
    const float aa0 = aa[0];

    for (int t0 = 0; t0 < CT; t0 += 64){
        const size_t rowbase = (size_t)b*CT + t0;
        for (int i = tid; i < 64*128; i += 256){
            int tt = i >> 7, c = i & 127;
            float v = g_proj[(rowbase+tt)*CPW + CR + c];
            if (c < 64) sB[tt][c] = v; else sC[tt][c-64] = v;
        }
        for (int i = tid; i < 64*16; i += 256){
            int tt = i >> 4, dd = i & 15;
            size_t r = rowbase + tt;
            sdel[tt][dd] = __half2float(g_del[r*CDI + dbase + dd]);
            su[tt][dd]   = __half2float(g_uca[r*CDI + dbase + dd]);
            sz[tt][dd]   = __half2float(g_xza[r*(2*CDI) + CDI + dbase + dd]);
        }
        __syncthreads();

        if (geo){
            #pragma unroll 2
            for (int tt=0; tt<64; tt++){
                float dlt = sdel[tt][dl];
                float u   = su[tt][dl];
                float du  = dlt * u;
                float4 Bv = *(const float4*)&sB[tt][q*4];
                float4 Cv = *(const float4*)&sC[tt][q*4];
                float e0 = ex2f(dlt*aa0);
                float rr = ex2f(dlt*step);
                float rr2 = rr*rr;
                float ev0 = e0, ev1 = e0*rr, ev2 = e0*rr2, ev3 = ev1*rr2;
                h[0] = h[0]*ev0 + du*Bv.x;
                h[1] = h[1]*ev1 + du*Bv.y;
                h[2] = h[2]*ev2 + du*Bv.z;
                h[3] = h[3]*ev3 + du*Bv.w;
                float yp = h[0]*Cv.x + h[1]*Cv.y + h[2]*Cv.z + h[3]*Cv.w;
                yp += __shfl_xor_sync(0xffffffffu, yp, 1);
                yp += __shfl_xor_sync(0xffffffffu, yp, 2);
                yp += __shfl_xor_sync(0xffffffffu, yp, 4);
                yp += __shfl_xor_sync(0xffffffffu, yp, 8);
                if (q == 0){
                    float z = sz[tt][dl];
                    float s = 1.f/(1.f + __expf(-z));
                    float v = (yp + u*Dd) * (z*s);
                    g_ya[(rowbase+tt)*CDI + d] = __float2half_rn(v);
                }
            }
        } else {
            #pragma unroll 2
            for (int tt=0; tt<64; tt++){
                float dlt = sdel[tt][dl];
                float u   = su[tt][dl];
                float du  = dlt * u;
                float4 Bv = *(const float4*)&sB[tt][q*4];
                float4 Cv = *(const float4*)&sC[tt][q*4];
                h[0] = h[0]*ex2f(dlt*aa[0]) + du*Bv.x;
                h[1] = h[1]*ex2f(dlt*aa[1]) + du*Bv.y;
                h[2] = h[2]*ex2f(dlt*aa[2]) + du*Bv.z;
                h[3] = h[3]*ex2f(dlt*aa[3]) + du*Bv.w;
                float yp = h[0]*Cv.x + h[1]*Cv.y + h[2]*Cv.z + h[3]*Cv.w;
                yp += __shfl_xor_sync(0xffffffffu, yp, 1);
                yp += __shfl_xor_sync(0xffffffffu, yp, 2);
                yp += __shfl_xor_sync(0xffffffffu, yp, 4);
                yp += __shfl_xor_sync(0xffffffffu, yp, 8);
                if (q == 0){
                    float z = sz[tt][dl];
                    float s = 1.f/(1.f + __expf(-z));
                    float v = (yp + u*Dd) * (z*s);
                    g_ya[(rowbase+tt)*CDI + d] = __float2half_rn(v);
                }
            }
        }
        __syncthreads();
    }
}

// ---------------- LayerNorm + FiLM + residual ----------------
__device__ __forceinline__ float blockReduceSum(float v){
    __shared__ float sh[8];
    __shared__ float tot;
    int lane = threadIdx.x & 31, w = threadIdx.x >> 5;
    #pragma unroll
    for (int o=16;o;o>>=1) v += __shfl_down_sync(0xffffffffu, v, o);
    if (!lane) sh[w] = v;
    __syncthreads();
    v = (threadIdx.x < 8) ? sh[threadIdx.x] : 0.f;
    if (w == 0){
        #pragma unroll
        for (int o=4;o;o>>=1) v += __shfl_down_sync(0xffffffffu, v, o);
    }
    if (threadIdx.x == 0) tot = v;
    __syncthreads();
    return tot;
}

template<int SPLIT>
__global__ void __launch_bounds__(256) ln_film_res_kernel(
    const float* __restrict__ gamma, const float* __restrict__ beta,
    const float* __restrict__ w, const float* __restrict__ bln,
    float* __restrict__ out)
{
    const int row = blockIdx.x;
    const int tid = threadIdx.x;
    const size_t base = (size_t)row*CDM;
    float v0 = g_ho[base+tid], v1 = g_ho[base+tid+256], v2 = g_ho[base+tid+512];
    float mean = blockReduceSum(v0+v1+v2) * (1.f/CDM);
    float d0 = v0-mean, d1 = v1-mean, d2 = v2-mean;
    float var = blockReduceSum(d0*d0 + d1*d1 + d2*d2) * (1.f/CDM);
    float rstd = rsqrtf(var + 1e-5f);
    float dv[3] = {d0, d1, d2};
    #pragma unroll
    for (int k=0;k<3;k++){
        int c = tid + k*256;
        float o = dv[k]*rstd*w[c] + bln[c];
        float v = gamma[base+c]*o + beta[base+c] + g_x[base+c];
        out[base+c] = v;
        if (SPLIT) g_xa[base+c] = __float2half_rn(v);
    }
}

// ---------------- launch ----------------
extern "C" void kernel_launch(void* const* d_in, const int* in_sizes, int n_in,
                              void* d_out, int out_size)
{
    (void)in_sizes; (void)n_in; (void)out_size;
    const float* x     = (const float*)d_in[0];
    const float* mask  = (const float*)d_in[1];
    const float* fgam  = (const float*)d_in[2];
    const float* fbet  = (const float*)d_in[3];
    const float* in_w  = (const float*)d_in[4];
    const float* cw    = (const float*)d_in[5];
    const float* cb    = (const float*)d_in[6];
    const float* xw    = (const float*)d_in[7];
    const float* dtw   = (const float*)d_in[8];
    const float* dtb   = (const float*)d_in[9];
    const float* alog  = (const float*)d_in[10];
    const float* Dp    = (const float*)d_in[11];
    const float* ow    = (const float*)d_in[12];
    const float* lnw   = (const float*)d_in[13];
    const float* lnb   = (const float*)d_in[14];

    float *gx, *gproj, *gho;
    cudaGetSymbolAddress((void**)&gx,   g_x);
    cudaGetSymbolAddress((void**)&gproj,g_proj);
    cudaGetSymbolAddress((void**)&gho,  g_ho);

    __half *xza, *xa, *uca, *dela, *dta, *ya, *iw, *xwp, *dw, *owp;
    cudaGetSymbolAddress((void**)&xza,  g_xza);
    cudaGetSymbolAddress((void**)&xa,   g_xa);
    cudaGetSymbolAddress((void**)&uca,  g_uca);
    cudaGetSymbolAddress((void**)&dela, g_del);
    cudaGetSymbolAddress((void**)&dta,  g_dta);
    cudaGetSymbolAddress((void**)&ya,   g_ya);
    cudaGetSymbolAddress((void**)&iw,   g_iw);
    cudaGetSymbolAddress((void**)&xwp,  g_xw);
    cudaGetSymbolAddress((void**)&dw,   g_dw);
    cudaGetSymbolAddress((void**)&owp,  g_ow);

    const int SMEM128 = 3*(128+128)*40*2;   // 61440 B
    const int SMEM64  = 3*(64+128)*40*2;    // 46080 B
    cudaFuncSetAttribute(gemm_f16<0,__half,128>, cudaFuncAttributeMaxDynamicSharedMemorySize, SMEM128);
    cudaFuncSetAttribute(gemm_f16<1,__half,128>, cudaFuncAttributeMaxDynamicSharedMemorySize, SMEM128);
    cudaFuncSetAttribute(gemm_f16<2,float,64>,   cudaFuncAttributeMaxDynamicSharedMemorySize, SMEM64);
    cudaFuncSetAttribute(gemm_f16<0,float,64>,   cudaFuncAttributeMaxDynamicSharedMemorySize, SMEM64);

    mask_kernel<<<(CBTDM + 255)/256, 256>>>(x, mask);
    {
        int n = NIW + NXW + NDW + NOW;
        wconv_all<<<(n+255)/256, 256>>>(in_w, xw, dtw, ow);
    }

    for (int l = 0; l < 2; l++){
        // xz = x @ W_in^T -> fp16  [8192 x 3072 x 768]  (BM=128)
        gemm_f16<0,__half,128><<<dim3(24,64), 256, SMEM128>>>(
            xa, CDM, iw + (size_t)l*NIW/2, CDM,
            xza, 2*CDI, CBT, 2*CDI, CDM, nullptr);
        // depthwise conv + silu
        conv_silu_kernel<<<((CBT/4)*(CDI/2) + 255)/256, 256>>>(cw + (size_t)l*CDI*4, cb + (size_t)l*CDI);
        // proj = u_c @ W_x^T -> fp32 (+ dt plane)  (BM=64, 256 CTAs)
        gemm_f16<2,float,64><<<dim3(2,128), 256, SMEM64>>>(
            uca, CDI, xwp + (size_t)l*NXW/2, CDI,
            gproj, CPW, CBT, CPW, CDI, nullptr);
        // delta = softplus(dt @ W_dt^T + b) -> fp16  (BM=128)
        gemm_f16<1,__half,128><<<dim3(12,64), 256, SMEM128>>>(
            dta, CR, dw + (size_t)l*NDW/2, CR,
            dela, CDI, CBT, CDI, CR, dtb + (size_t)l*CDI);
        // selective scan -> fp16 y  (256 threads, 16 lanes/channel)
        scan_kernel<<<dim3(CDI/16, CB), 256>>>(alog + (size_t)l*CDI*CN, Dp + (size_t)l*CDI);
        // h_out = y @ W_out^T -> fp32  (BM=64, 768 CTAs)
        gemm_f16<0,float,64><<<dim3(6,128), 256, SMEM64>>>(
            ya, CDI, owp + (size_t)l*NOW/2, CDI,
            gho, CDM, CBT, CDM, CDI, nullptr);
        // LN + FiLM + residual
        if (l == 0)
            ln_film_res_kernel<1><<<CBT, 256>>>(fgam, fbet, lnw, lnb, gx);
        else
            ln_film_res_kernel<0><<<CBT, 256>>>(fgam + (size_t)CBTDM, fbet + (size_t)CBTDM,
                                                lnw + CDM, lnb + CDM, (float*)d_out);
    }
}